// round 2
// baseline (speedup 1.0000x reference)
#include <cuda_runtime.h>
#include <cuda_bf16.h>

// Shapes fixed by setup_inputs
#define BATCH 8
#define L 128
#define D 768
#define NF4 (D / 4)                  // 192 float4 per row
#define NROW (BATCH * L * L)         // 131072
#define PER_B (L * L)                // 16384
#define K1_BLOCKS 1024
#define K1_WARPS 8
#define QPW (NROW / (K1_BLOCKS * K1_WARPS * 4))   // quads per warp = 4

// Device scratch (no allocations allowed)
__device__ unsigned g_keyS[NROW];
__device__ unsigned g_keyE[NROW];
__device__ float    g_partS[K1_BLOCKS];
__device__ float    g_partE[K1_BLOCKS];

// order-preserving float->uint encoding (monotonic over all floats)
__device__ __forceinline__ unsigned enc_f32(float f)
{
    unsigned u = __float_as_uint(f);
    return (u & 0x80000000u) ? ~u : (u | 0x80000000u);
}

// ---------------------------------------------------------------------------
// K1: fused dual GEMV + BCE partials + encoded sigmoid keys.
// Each warp handles 4 rows at a time: 8 lanes per row, 24 float4 per lane.
//  - 24 independent LDG.128 per lane -> high MLP
//  - row reduction is only 3 shuffles (within 8-lane groups)
// ---------------------------------------------------------------------------
__global__ __launch_bounds__(256) void k_main(
    const float* __restrict__ table,
    const float* __restrict__ W_S, const float* __restrict__ bSp,
    const float* __restrict__ W_E, const float* __restrict__ bEp,
    const int* __restrict__ labS, const int* __restrict__ labE)
{
    __shared__ float4 sWs[NF4];
    __shared__ float4 sWe[NF4];
    __shared__ float  redS[K1_WARPS];
    __shared__ float  redE[K1_WARPS];

    for (int i = threadIdx.x; i < NF4; i += 256) {
        sWs[i] = ((const float4*)W_S)[i];
        sWe[i] = ((const float4*)W_E)[i];
    }
    __syncthreads();

    const int warp = threadIdx.x >> 5;
    const int lane = threadIdx.x & 31;
    const int sub  = lane >> 3;       // row within quad (0..3)
    const int o    = lane & 7;        // float4 offset base (0..7)
    const float biasS = bSp[0];
    const float biasE = bEp[0];

    const int gw = blockIdx.x * K1_WARPS + warp;   // global warp id

    float accS = 0.f, accE = 0.f;

#pragma unroll 1
    for (int qq = 0; qq < QPW; qq++) {
        const long long row = ((long long)gw * QPW + qq) * 4 + sub;
        const float4* __restrict__ t = (const float4*)table + row * NF4;

        float sS = 0.f, sE = 0.f;
#pragma unroll
        for (int j = 0; j < 24; j++) {
            const int idx = o + 8 * j;
            float4 v = t[idx];
            float4 a = sWs[idx];
            float4 b = sWe[idx];
            sS += v.x * a.x + v.y * a.y + v.z * a.z + v.w * a.w;
            sE += v.x * b.x + v.y * b.y + v.z * b.z + v.w * b.w;
        }
        // reduce within each 8-lane group (groups are xor-aligned)
#pragma unroll
        for (int off = 1; off < 8; off <<= 1) {
            sS += __shfl_xor_sync(0xFFFFFFFFu, sS, off);
            sE += __shfl_xor_sync(0xFFFFFFFFu, sE, off);
        }
        if (o == 0) {
            const float lS = sS + biasS;
            const float lE = sE + biasE;
            const int tS = labS[row];
            const int tE = labE[row];
            const float w = (tS >= 0) ? 1.0f : 0.0f;
            // stable BCE-with-logits
            accS += w * (fmaxf(lS, 0.f) - lS * (float)tS + log1pf(expf(-fabsf(lS))));
            accE += w * (fmaxf(lE, 0.f) - lE * (float)tE + log1pf(expf(-fabsf(lE))));
            g_keyS[row] = enc_f32(w / (1.0f + expf(-lS)));
            g_keyE[row] = enc_f32(w / (1.0f + expf(-lE)));
        }
    }

    // combine the 4 per-row-lane accumulators (lanes 0,8,16,24; others hold 0)
    accS += __shfl_xor_sync(0xFFFFFFFFu, accS, 8);
    accE += __shfl_xor_sync(0xFFFFFFFFu, accE, 8);
    accS += __shfl_xor_sync(0xFFFFFFFFu, accS, 16);
    accE += __shfl_xor_sync(0xFFFFFFFFu, accE, 16);

    if (lane == 0) { redS[warp] = accS; redE[warp] = accE; }
    __syncthreads();
    if (threadIdx.x == 0) {
        float a = 0.f, b = 0.f;
#pragma unroll
        for (int i = 0; i < K1_WARPS; i++) { a += redS[i]; b += redE[i]; }
        g_partS[blockIdx.x] = a;
        g_partE[blockIdx.x] = b;
    }
}

// ---------------------------------------------------------------------------
// K2: fused post-processing, one launch, 17 blocks x 512 threads.
//  blocks 0-15 : per-(batch, head) radix select with all 16K keys held in
//                REGISTERS (32/thread); 4 passes; then write predict mask
//                directly from the registers. Zero global re-reads.
//  block 16    : deterministic loss reduction -> out[0], out[1]
// out layout: [loss_S, loss_E, predict_S(131072), predict_E(131072)]
// ---------------------------------------------------------------------------
__global__ __launch_bounds__(512) void k_post(const int* __restrict__ amask,
                                              float* __restrict__ out)
{
    const int tid = threadIdx.x;

    if (blockIdx.x == 16) {
        __shared__ float sA[512];
        __shared__ float sB[512];
        float a = 0.f, b = 0.f;
        for (int i = tid; i < K1_BLOCKS; i += 512) { a += g_partS[i]; b += g_partE[i]; }
        sA[tid] = a; sB[tid] = b;
        __syncthreads();
        for (int s = 256; s; s >>= 1) {
            if (tid < s) { sA[tid] += sA[tid + s]; sB[tid] += sB[tid + s]; }
            __syncthreads();
        }
        if (tid == 0) {
            out[0] = sA[0] / (float)NROW;
            out[1] = sB[0] / (float)NROW;
        }
        return;
    }

    const int b    = blockIdx.x & 7;
    const int head = blockIdx.x >> 3;   // 0 = S, 1 = E
    const unsigned* __restrict__ keys = (head == 0 ? g_keyS : g_keyE) + b * PER_B;

    // pull all 16384 keys of this (batch, head) into registers, coalesced
    unsigned k[32];
#pragma unroll
    for (int i = 0; i < 32; i++) k[i] = keys[tid + 512 * i];

    __shared__ int      s_hist[256];
    __shared__ int      s_mask[L];
    __shared__ unsigned s_prefix;
    __shared__ unsigned s_pmask;
    __shared__ int      s_k;

    if (tid < L) s_mask[tid] = amask[b * L + tid];
    __syncthreads();

    if (tid == 0) {
        int msum = 0;
#pragma unroll
        for (int i = 0; i < L; i++) msum += s_mask[i];
        const int mlen = msum - 2;
        int len = (int)((float)mlen * 0.3f);   // trunc like .astype(int32)
        if (len < 5) len = 5;
        const int mlsq = mlen * mlen;
        if (len > mlsq) len = mlsq;
        if (len < 1) len = 1;
        if (len > PER_B) len = PER_B;
        s_k = len;
        s_prefix = 0u;
        s_pmask = 0u;
    }
    __syncthreads();

    for (int pass = 3; pass >= 0; pass--) {
        const int shift = pass * 8;
        if (tid < 256) s_hist[tid] = 0;
        __syncthreads();
        const unsigned pm = s_pmask;
        const unsigned pf = s_prefix;
#pragma unroll
        for (int i = 0; i < 32; i++)
            if ((k[i] & pm) == pf) atomicAdd(&s_hist[(k[i] >> shift) & 0xFFu], 1);
        __syncthreads();
        if (tid == 0) {
            const int kk = s_k;
            int cum = 0;
            int c = 255;
            for (; c > 0; c--) {
                if (cum + s_hist[c] >= kk) break;
                cum += s_hist[c];
            }
            s_k = kk - cum;
            s_prefix = pf | ((unsigned)c << shift);
            s_pmask = pm | (0xFFu << shift);
        }
        __syncthreads();
    }

    // s_prefix is exactly the encoded k-th largest key; key >= thr is
    // bit-identical to the reference's pred >= topkth comparison
    const unsigned thr = s_prefix;
    float* __restrict__ o = out + 2 + head * NROW + b * PER_B;
#pragma unroll
    for (int i = 0; i < 32; i++)
        o[tid + 512 * i] = (k[i] >= thr) ? 1.0f : 0.0f;
}

// ---------------------------------------------------------------------------
extern "C" void kernel_launch(void* const* d_in, const int* in_sizes, int n_in,
                              void* d_out, int out_size)
{
    const float* table = (const float*)d_in[0];
    const int*   amask = (const int*)d_in[1];
    const int*   labS  = (const int*)d_in[2];
    const int*   labE  = (const int*)d_in[3];
    const float* W_S   = (const float*)d_in[4];
    const float* b_S   = (const float*)d_in[5];
    const float* W_E   = (const float*)d_in[6];
    const float* b_E   = (const float*)d_in[7];
    float* out = (float*)d_out;

    k_main<<<K1_BLOCKS, 256>>>(table, W_S, b_S, W_E, b_E, labS, labE);
    k_post<<<17, 512>>>(amask, out);
}